// round 3
// baseline (speedup 1.0000x reference)
#include <cuda_runtime.h>
#include <cuda_bf16.h>

// ---------------- problem constants ----------------
constexpr int N_NODES  = 50000;
constexpr int N_EDGES  = 1600000;
constexpr int F_IN     = 64;
constexpr int F_HID    = 128;
constexpr int F_LAT    = 32;
constexpr int N_HARM   = 8;
constexpr int N_LAYERS = 3;
constexpr int N_GRAPHS = 64;

constexpr int SZ_WTE  = F_IN  * 16 * F_HID;              // 131072  (K=1024 x 128)
constexpr int SZ_WTMP = N_LAYERS * F_HID * 16 * F_HID;   // 786432  (3 x K=2048 x 128)
constexpr int SZ_WTR  = F_HID * 16 * F_LAT;              // 65536   (K=2048 x 32)

// ---------------- scratch (static device memory; no allocs allowed) ----------------
__device__ float g_h0[N_NODES * F_HID];
__device__ float g_h1[N_NODES * F_HID];
__device__ float g_deg[N_NODES];
__device__ float g_dinv[N_NODES];
__device__ float g_pool[N_GRAPHS * F_HID];
__device__ float g_cnt[N_GRAPHS];
__device__ float g_WtE[SZ_WTE];
__device__ float g_WtMP[SZ_WTMP];
__device__ float g_WtR[SZ_WTR];

typedef unsigned long long ull;

// ---------------- packed fp32x2 helpers (Blackwell FFMA2 path) ----------------
__device__ __forceinline__ ull pack_dup(float v) {
    ull r; asm("mov.b64 %0, {%1, %1};" : "=l"(r) : "f"(v)); return r;
}
__device__ __forceinline__ void unpack2(ull v, float& lo, float& hi) {
    asm("mov.b64 {%0, %1}, %2;" : "=f"(lo), "=f"(hi) : "l"(v));
}
__device__ __forceinline__ void ffma2(ull& d, ull a, ull b) {
    asm("fma.rn.f32x2 %0, %1, %2, %0;" : "+l"(d) : "l"(a), "l"(b));
}
__device__ __forceinline__ void red_add_v4(float* p, float4 v) {
    asm volatile("red.global.add.v4.f32 [%0], {%1, %2, %3, %4};"
                 :: "l"(p), "f"(v.x), "f"(v.y), "f"(v.z), "f"(v.w) : "memory");
}
__device__ __forceinline__ void red_add_f32(float* p, float v) {
    asm volatile("red.global.add.f32 [%0], %1;" :: "l"(p), "f"(v) : "memory");
}

// ---------------- weight pre-transpose: W[2][out][in][H] -> Wt[k][out], k = i*16 + trig*8 + h ----------------
__global__ void prep_weights(const float* __restrict__ We,
                             const float* __restrict__ Wm,
                             const float* __restrict__ Wr)
{
    int idx = blockIdx.x * blockDim.x + threadIdx.x;
    if (idx < SZ_WTE) {
        int k = idx >> 7, o = idx & 127;
        int i = k >> 4, t = (k >> 3) & 1, hm = k & 7;
        g_WtE[idx] = We[((t * F_HID + o) * F_IN + i) * N_HARM + hm];
    } else if (idx < SZ_WTE + SZ_WTMP) {
        int rel = idx - SZ_WTE;
        int lay = rel / (F_HID * 16 * F_HID);
        int r2  = rel % (F_HID * 16 * F_HID);
        int k = r2 >> 7, o = r2 & 127;
        int i = k >> 4, t = (k >> 3) & 1, hm = k & 7;
        g_WtMP[rel] = Wm[(((lay * 2 + t) * F_HID + o) * F_HID + i) * N_HARM + hm];
    } else if (idx < SZ_WTE + SZ_WTMP + SZ_WTR) {
        int rel = idx - SZ_WTE - SZ_WTMP;
        int k = rel / F_LAT, o = rel % F_LAT;
        int i = k >> 4, t = (k >> 3) & 1, hm = k & 7;
        g_WtR[rel] = Wr[((t * F_LAT + o) * F_HID + i) * N_HARM + hm];
    }
}

// ---------------- degree / norm ----------------
__global__ void deg_init_kernel() {
    int i = blockIdx.x * blockDim.x + threadIdx.x;
    if (i < N_NODES) g_deg[i] = 1.0f;               // self-loop
}
__global__ void deg_edge_kernel(const int* __restrict__ col) {
    int e = blockIdx.x * blockDim.x + threadIdx.x;
    if (e < N_EDGES) red_add_f32(&g_deg[col[e]], 1.0f);   // REDG: no-return reduction
}
__global__ void dinv_kernel() {
    int i = blockIdx.x * blockDim.x + threadIdx.x;
    if (i < N_NODES) g_dinv[i] = rsqrtf(g_deg[i]);
}

// ---------------- fused KAN GEMM: out[N,128] = [cos|sin features of x] @ Wt ----------------
// Block tile: 64 nodes x 128 outs. 256 threads. Warp w -> nodes [w*8, w*8+8),
// lane l -> outs [l*4, l*4+4). Accumulate node-PAIRS in packed f32x2 (FFMA2).
// Weight chunks are prefetched 1 iteration ahead into registers to hide L2 latency.
template<int C>
__global__ __launch_bounds__(256, 2)
void kan_gemm(const float* __restrict__ x, const float* __restrict__ Wt,
              float* __restrict__ out, int nRows)
{
    __shared__ __align__(16) float As[32][64];    // generated features: k-chunk x nodes
    __shared__ __align__(16) float Bs[32][128];   // weight chunk: k x out

    const int tid = threadIdx.x;
    const int m0  = blockIdx.x * 64;
    const int w   = tid >> 5;
    const int l   = tid & 31;
    const int nb  = w * 8;    // node base within tile
    const int ob  = l * 4;    // out base

    ull acc[4][4];
    #pragma unroll
    for (int p = 0; p < 4; p++)
        #pragma unroll
        for (int o = 0; o < 4; o++) acc[p][o] = 0ull;

    // prefetch first weight chunk into registers
    float4 wreg[4];
    #pragma unroll
    for (int j = 0; j < 4; j++)
        wreg[j] = *(const float4*)(Wt + tid * 4 + j * 1024);

    for (int ic = 0; ic < C; ic += 2) {
        __syncthreads();   // previous compute done; safe to overwrite As/Bs
        // --- store prefetched weight chunk ---
        {
            float* bs = &Bs[0][0];
            #pragma unroll
            for (int j = 0; j < 4; j++)
                *(float4*)(bs + tid * 4 + j * 1024) = wreg[j];
        }
        // --- generate cos/sin harmonics for inputs ic, ic+1 (Chebyshev recurrence) ---
        if (tid < 128) {
            const int node = tid & 63;
            const int io   = tid >> 6;
            const int gn   = m0 + node;
            float xv = (gn < nRows) ? x[gn * C + ic + io] : 0.f;
            float s1, c1;
            sincosf(xv, &s1, &c1);
            const int kb = io << 4;
            As[kb + 0][node] = c1;
            As[kb + 8][node] = s1;
            const float c2 = 2.f * c1;
            float cp = 1.f, sp = 0.f, cc = c1, sc = s1;
            #pragma unroll
            for (int h = 1; h < 8; h++) {
                float cn = fmaf(c2, cc, -cp);
                float sn = fmaf(c2, sc, -sp);
                As[kb + h][node]     = cn;
                As[kb + 8 + h][node] = sn;
                cp = cc; cc = cn; sp = sc; sc = sn;
            }
        }
        __syncthreads();
        // --- prefetch NEXT weight chunk (completes under the FFMA2 phase) ---
        if (ic + 2 < C) {
            const float* wsrc = Wt + (ic + 2) * (16 * 128);
            #pragma unroll
            for (int j = 0; j < 4; j++)
                wreg[j] = *(const float4*)(wsrc + tid * 4 + j * 1024);
        }
        // --- FFMA2 micro-kernel: 32 k-steps x (4 node-pairs x 4 outs) ---
        #pragma unroll 8
        for (int kk = 0; kk < 32; kk++) {
            ull a0 = *(const ull*)&As[kk][nb + 0];
            ull a1 = *(const ull*)&As[kk][nb + 2];
            ull a2 = *(const ull*)&As[kk][nb + 4];
            ull a3 = *(const ull*)&As[kk][nb + 6];
            float4 b = *(const float4*)&Bs[kk][ob];
            ull b0 = pack_dup(b.x), b1 = pack_dup(b.y), b2 = pack_dup(b.z), b3 = pack_dup(b.w);
            ffma2(acc[0][0], a0, b0); ffma2(acc[0][1], a0, b1); ffma2(acc[0][2], a0, b2); ffma2(acc[0][3], a0, b3);
            ffma2(acc[1][0], a1, b0); ffma2(acc[1][1], a1, b1); ffma2(acc[1][2], a1, b2); ffma2(acc[1][3], a1, b3);
            ffma2(acc[2][0], a2, b0); ffma2(acc[2][1], a2, b1); ffma2(acc[2][2], a2, b2); ffma2(acc[2][3], a2, b3);
            ffma2(acc[3][0], a3, b0); ffma2(acc[3][1], a3, b1); ffma2(acc[3][2], a3, b2); ffma2(acc[3][3], a3, b3);
        }
    }

    #pragma unroll
    for (int p = 0; p < 4; p++) {
        float lo0, hi0, lo1, hi1, lo2, hi2, lo3, hi3;
        unpack2(acc[p][0], lo0, hi0);
        unpack2(acc[p][1], lo1, hi1);
        unpack2(acc[p][2], lo2, hi2);
        unpack2(acc[p][3], lo3, hi3);
        int n0 = m0 + nb + 2 * p;
        if (n0 < nRows)
            *(float4*)&out[n0 * F_HID + ob] = make_float4(lo0, lo1, lo2, lo3);
        if (n0 + 1 < nRows)
            *(float4*)&out[(n0 + 1) * F_HID + ob] = make_float4(hi0, hi1, hi2, hi3);
    }
}

// ---------------- symmetric-normalized scatter-add (warp per edge) ----------------
__global__ void scatter_kernel(const float* __restrict__ t, float* __restrict__ agg,
                               const int* __restrict__ row, const int* __restrict__ col)
{
    unsigned int gid = blockIdx.x * blockDim.x + threadIdx.x;
    int gw   = (int)(gid >> 5);
    int lane = threadIdx.x & 31;
    if (gw >= N_EDGES + N_NODES) return;
    int r, c;
    if (gw < N_EDGES) { r = __ldg(&row[gw]); c = __ldg(&col[gw]); }
    else              { r = c = gw - N_EDGES; }    // self loop
    float norm = g_dinv[r] * g_dinv[c];
    float4 v = *(const float4*)&t[r * F_HID + lane * 4];
    v.x *= norm; v.y *= norm; v.z *= norm; v.w *= norm;
    red_add_v4(&agg[c * F_HID + lane * 4], v);
}

// ---------------- zero fill ----------------
__global__ void zero_kernel(float* __restrict__ p, int n) {
    int i = (blockIdx.x * blockDim.x + threadIdx.x) * 4;
    if (i < n) *(float4*)&p[i] = make_float4(0.f, 0.f, 0.f, 0.f);
}

// ---------------- global mean pool (sum + count) ----------------
__global__ void pool_kernel(const float* __restrict__ h, const int* __restrict__ batch)
{
    int idx  = blockIdx.x * blockDim.x + threadIdx.x;
    int node = idx >> 5, q = idx & 31;
    if (node >= N_NODES) return;
    int g = __ldg(&batch[node]);
    float4 v = *(const float4*)&h[node * F_HID + q * 4];
    red_add_v4(&g_pool[g * F_HID + q * 4], v);
    if (q == 0) red_add_f32(&g_cnt[g], 1.0f);
}

// ---------------- readout: mean -> KAN -> out[G, LAT] ----------------
__global__ void readout_kernel(float* __restrict__ out)
{
    __shared__ float feat[F_HID * 16];   // 2048 generated features
    __shared__ float rbuf[8][F_LAT];
    int g = blockIdx.x, tid = threadIdx.x;
    if (tid < F_HID) {
        float cnt = fmaxf(g_cnt[g], 1.0f);
        float xv  = g_pool[g * F_HID + tid] / cnt;
        float s1, c1;
        sincosf(xv, &s1, &c1);
        int kb = tid * 16;
        feat[kb + 0] = c1; feat[kb + 8] = s1;
        float c2 = 2.f * c1, cp = 1.f, sp = 0.f, cc = c1, sc = s1;
        #pragma unroll
        for (int h = 1; h < 8; h++) {
            float cn = fmaf(c2, cc, -cp);
            float sn = fmaf(c2, sc, -sp);
            feat[kb + h] = cn; feat[kb + 8 + h] = sn;
            cp = cc; cc = cn; sp = sc; sc = sn;
        }
    }
    __syncthreads();
    int o = tid & 31, part = tid >> 5;
    float sum = 0.f;
    int k0 = part * 256;
    #pragma unroll 8
    for (int k = k0; k < k0 + 256; k++)
        sum = fmaf(feat[k], g_WtR[k * F_LAT + o], sum);
    rbuf[part][o] = sum;
    __syncthreads();
    if (tid < F_LAT) {
        float s = 0.f;
        #pragma unroll
        for (int p = 0; p < 8; p++) s += rbuf[p][tid];
        out[g * F_LAT + tid] = s;
    }
}

// ---------------- launch ----------------
extern "C" void kernel_launch(void* const* d_in, const int* in_sizes, int n_in,
                              void* d_out, int out_size)
{
    const float* features = (const float*)d_in[0];
    const int*   ei       = (const int*)d_in[1];
    const int*   batch    = (const int*)d_in[2];
    const float* W_embed  = (const float*)d_in[3];
    const float* W_mp     = (const float*)d_in[4];
    const float* W_read   = (const float*)d_in[5];
    float*       out      = (float*)d_out;

    const int* row = ei;
    const int* col = ei + N_EDGES;

    float *p_h0, *p_h1, *p_WtE, *p_WtMP, *p_pool, *p_cnt;
    cudaGetSymbolAddress((void**)&p_h0,   g_h0);
    cudaGetSymbolAddress((void**)&p_h1,   g_h1);
    cudaGetSymbolAddress((void**)&p_WtE,  g_WtE);
    cudaGetSymbolAddress((void**)&p_WtMP, g_WtMP);
    cudaGetSymbolAddress((void**)&p_pool, g_pool);
    cudaGetSymbolAddress((void**)&p_cnt,  g_cnt);

    // weights -> k-major transposed copies
    prep_weights<<<(SZ_WTE + SZ_WTMP + SZ_WTR + 255) / 256, 256>>>(W_embed, W_mp, W_read);

    // degrees (self-loops included) and d^-1/2
    deg_init_kernel<<<(N_NODES + 255) / 256, 256>>>();
    deg_edge_kernel<<<(N_EDGES + 255) / 256, 256>>>(col);
    dinv_kernel<<<(N_NODES + 255) / 256, 256>>>();

    const int gemm_blocks = (N_NODES + 63) / 64;

    // embed
    kan_gemm<F_IN><<<gemm_blocks, 256>>>(features, p_WtE, p_h0, N_NODES);

    // message-passing layers: kan -> normalized scatter-add
    for (int lay = 0; lay < N_LAYERS; lay++) {
        kan_gemm<F_HID><<<gemm_blocks, 256>>>(p_h0, p_WtMP + lay * (F_HID * 16 * F_HID), p_h1, N_NODES);
        zero_kernel<<<(N_NODES * F_HID / 4 + 255) / 256, 256>>>(p_h0, N_NODES * F_HID);
        scatter_kernel<<<((unsigned)(N_EDGES + N_NODES) * 32 + 255) / 256, 256>>>(p_h1, p_h0, row, col);
    }

    // mean pool + readout
    zero_kernel<<<(N_GRAPHS * F_HID / 4 + 255) / 256, 256>>>(p_pool, N_GRAPHS * F_HID);
    zero_kernel<<<1, 16>>>(p_cnt, N_GRAPHS);
    pool_kernel<<<((unsigned)N_NODES * 32 + 255) / 256, 256>>>(p_h0, batch);
    readout_kernel<<<N_GRAPHS, 256>>>(out);
}

// round 10
// speedup vs baseline: 1.2007x; 1.2007x over previous
#include <cuda_runtime.h>
#include <cuda_bf16.h>
#include <cstdint>

// ---------------- problem constants ----------------
constexpr int N_NODES  = 50000;
constexpr int N_EDGES  = 1600000;
constexpr int F_IN     = 64;
constexpr int F_HID    = 128;
constexpr int F_LAT    = 32;
constexpr int N_HARM   = 8;
constexpr int N_LAYERS = 3;
constexpr int N_GRAPHS = 64;

constexpr int SZ_WTE  = F_IN  * 16 * F_HID;              // 131072  (K=1024 x 128)
constexpr int SZ_WTMP = N_LAYERS * F_HID * 16 * F_HID;   // 786432  (3 x K=2048 x 128)
constexpr int SZ_WTR  = F_HID * 16 * F_LAT;              // 65536   (K=2048 x 32)

constexpr int BS_PAD = 136;   // row stride (words) for Bs: bank (8*tig+g)%32 bijective
constexpr int AS_PAD = 36;    // row stride (words) for As: bank (4*g+tig)%32 bijective

// dynamic SMEM layout (words): AsH | AsL | BsH | BsL
constexpr int AS_WORDS   = 128 * AS_PAD;      // 4608
constexpr int BS_WORDS   = 32 * BS_PAD;       // 4352
constexpr int SMEM_WORDS = 2 * AS_WORDS + 2 * BS_WORDS;   // 17920
constexpr int SMEM_BYTES = SMEM_WORDS * 4;                // 71680

// ---------------- scratch (static device memory; no allocs allowed) ----------------
__device__ float g_h0[N_NODES * F_HID];
__device__ float g_h1[N_NODES * F_HID];
__device__ float g_deg[N_NODES];
__device__ float g_dinv[N_NODES];
__device__ float g_pool[N_GRAPHS * F_HID];
__device__ float g_cnt[N_GRAPHS];
__device__ float g_WtE_hi[SZ_WTE],  g_WtE_lo[SZ_WTE];
__device__ float g_WtMP_hi[SZ_WTMP], g_WtMP_lo[SZ_WTMP];
__device__ float g_WtR[SZ_WTR];

// ---------------- helpers ----------------
__device__ __forceinline__ void red_add_v4(float* p, float4 v) {
    asm volatile("red.global.add.v4.f32 [%0], {%1, %2, %3, %4};"
                 :: "l"(p), "f"(v.x), "f"(v.y), "f"(v.z), "f"(v.w) : "memory");
}
__device__ __forceinline__ void red_add_f32(float* p, float v) {
    asm volatile("red.global.add.f32 [%0], %1;" :: "l"(p), "f"(v) : "memory");
}
__device__ __forceinline__ uint32_t to_tf32(float f) {
    uint32_t u;
    asm("cvt.rna.tf32.f32 %0, %1;" : "=r"(u) : "f"(f));
    return u;
}
__device__ __forceinline__ float to_tf32f(float f) {
    return __uint_as_float(to_tf32(f));
}
// mma.sync m16n8k8 tf32: D = A*B + C (C==D registers)
__device__ __forceinline__ void mma_tf32(float* c, const uint32_t* a, uint32_t b0, uint32_t b1) {
    asm volatile(
        "mma.sync.aligned.m16n8k8.row.col.f32.tf32.tf32.f32 "
        "{%0,%1,%2,%3}, {%4,%5,%6,%7}, {%8,%9}, {%0,%1,%2,%3};"
        : "+f"(c[0]), "+f"(c[1]), "+f"(c[2]), "+f"(c[3])
        : "r"(a[0]), "r"(a[1]), "r"(a[2]), "r"(a[3]), "r"(b0), "r"(b1));
}
__device__ __forceinline__ void cp_async16(void* smem_ptr, const void* gptr) {
    uint32_t s = (uint32_t)__cvta_generic_to_shared(smem_ptr);
    asm volatile("cp.async.ca.shared.global [%0], [%1], 16;" :: "r"(s), "l"(gptr));
}
__device__ __forceinline__ void cp_commit() { asm volatile("cp.async.commit_group;"); }
__device__ __forceinline__ void cp_wait0()  { asm volatile("cp.async.wait_group 0;"); }

// ---------------- weight prep: transpose to k-major AND split into tf32 hi/lo ----------------
// Wt[k][o], k = i*16 + trig*8 + (harm-1).  hi = tf32RN(w), lo = tf32RN(w - hi).
__global__ void prep_weights(const float* __restrict__ We,
                             const float* __restrict__ Wm,
                             const float* __restrict__ Wr)
{
    int idx = blockIdx.x * blockDim.x + threadIdx.x;
    if (idx < SZ_WTE) {
        int k = idx >> 7, o = idx & 127;
        int i = k >> 4, t = (k >> 3) & 1, hm = k & 7;
        float w = We[((t * F_HID + o) * F_IN + i) * N_HARM + hm];
        float hi = to_tf32f(w);
        g_WtE_hi[idx] = hi;
        g_WtE_lo[idx] = to_tf32f(w - hi);
    } else if (idx < SZ_WTE + SZ_WTMP) {
        int rel = idx - SZ_WTE;
        int lay = rel / (F_HID * 16 * F_HID);
        int r2  = rel % (F_HID * 16 * F_HID);
        int k = r2 >> 7, o = r2 & 127;
        int i = k >> 4, t = (k >> 3) & 1, hm = k & 7;
        float w = Wm[(((lay * 2 + t) * F_HID + o) * F_HID + i) * N_HARM + hm];
        float hi = to_tf32f(w);
        g_WtMP_hi[rel] = hi;
        g_WtMP_lo[rel] = to_tf32f(w - hi);
    } else if (idx < SZ_WTE + SZ_WTMP + SZ_WTR) {
        int rel = idx - SZ_WTE - SZ_WTMP;
        int k = rel / F_LAT, o = rel % F_LAT;
        int i = k >> 4, t = (k >> 3) & 1, hm = k & 7;
        g_WtR[rel] = Wr[((t * F_LAT + o) * F_HID + i) * N_HARM + hm];
    }
}

// ---------------- degree / norm ----------------
__global__ void deg_init_kernel() {
    int i = blockIdx.x * blockDim.x + threadIdx.x;
    if (i < N_NODES) g_deg[i] = 1.0f;               // self-loop
}
__global__ void deg_edge_kernel(const int* __restrict__ col) {
    int e = blockIdx.x * blockDim.x + threadIdx.x;
    if (e < N_EDGES) red_add_f32(&g_deg[col[e]], 1.0f);
}
__global__ void dinv_kernel() {
    int i = blockIdx.x * blockDim.x + threadIdx.x;
    if (i < N_NODES) g_dinv[i] = rsqrtf(g_deg[i]);
}

// ---------------- fused KAN GEMM (3xTF32 split-precision tensor cores) ----------------
// out[N,128] = [cos|sin harmonics of x] @ W, fp32-accurate via hi/lo decomposition:
//   acc += a_lo*b_hi; acc += a_hi*b_lo; acc += a_hi*b_hi   (a_lo*b_lo ~ 2^-22, dropped)
// Block: 128 nodes x 128 outs, 256 threads (8 warps, 4x2 warp tiles of 32x64).
template<int C>
__global__ __launch_bounds__(256, 2)
void kan_gemm_mma(const float* __restrict__ x,
                  const float* __restrict__ WtHi, const float* __restrict__ WtLo,
                  float* __restrict__ out, int nRows)
{
    extern __shared__ __align__(16) uint32_t dynsmem[];
    uint32_t* AsH = dynsmem;                       // [128][AS_PAD]
    uint32_t* AsL = AsH + AS_WORDS;                // [128][AS_PAD]
    float*    BsH = (float*)(AsL + AS_WORDS);      // [32][BS_PAD]
    float*    BsL = BsH + BS_WORDS;                // [32][BS_PAD]

    const int tid  = threadIdx.x;
    const int m0   = blockIdx.x * 128;
    const int wid  = tid >> 5;
    const int lane = tid & 31;
    const int g    = lane >> 2;       // 0..7
    const int tig  = lane & 3;        // 0..3
    const int mbase = (wid & 3) * 32;
    const int nbase = (wid >> 2) * 64;

    float acc[2][8][4];
    #pragma unroll
    for (int m = 0; m < 2; m++)
        #pragma unroll
        for (int n = 0; n < 8; n++)
            #pragma unroll
            for (int r = 0; r < 4; r++) acc[m][n][r] = 0.f;

    const int node = tid & 127;
    const int ch   = tid >> 7;        // 0 or 1
    const int gn   = m0 + node;
    const bool vld = gn < nRows;

    // weight-copy addressing: thread copies 4x16B per buffer, row k0+8j, cols n0..n0+3
    const int n0 = lane * 4;
    const int k0 = wid;

    for (int ic = 0; ic < C; ic += 2) {
        __syncthreads();   // previous chunk's MMA reads done; SMEM free
        // --- async-copy this chunk's weights into BsH/BsL (overlaps feature gen) ---
        {
            const float* srcH = WtHi + ic * 2048;
            const float* srcL = WtLo + ic * 2048;
            #pragma unroll
            for (int j = 0; j < 4; j++) {
                int gidx = (k0 + 8 * j) * 128 + n0;
                cp_async16(&BsH[(k0 + 8 * j) * BS_PAD + n0], srcH + gidx);
                cp_async16(&BsL[(k0 + 8 * j) * BS_PAD + n0], srcL + gidx);
            }
            cp_commit();
        }
        // --- generate 16 harmonic features (hi/lo) for (node, channel ic+ch) ---
        {
            float xv = vld ? x[gn * C + ic + ch] : 0.f;
            float s1, c1;
            sincosf(xv, &s1, &c1);
            float vr[16];
            vr[0] = c1; vr[8] = s1;
            const float c2 = 2.f * c1;
            float cp = 1.f, sp = 0.f, cc = c1, sc = s1;
            #pragma unroll
            for (int h = 1; h < 8; h++) {
                float cn = fmaf(c2, cc, -cp);
                float sn = fmaf(c2, sc, -sp);
                vr[h] = cn; vr[8 + h] = sn;
                cp = cc; cc = cn; sp = sc; sc = sn;
            }
            uint32_t vh[16], vl[16];
            #pragma unroll
            for (int i = 0; i < 16; i++) {
                vh[i] = to_tf32(vr[i]);
                vl[i] = to_tf32(vr[i] - __uint_as_float(vh[i]));
            }
            uint4* dh = (uint4*)&AsH[node * AS_PAD + ch * 16];
            dh[0] = make_uint4(vh[0],  vh[1],  vh[2],  vh[3]);
            dh[1] = make_uint4(vh[4],  vh[5],  vh[6],  vh[7]);
            dh[2] = make_uint4(vh[8],  vh[9],  vh[10], vh[11]);
            dh[3] = make_uint4(vh[12], vh[13], vh[14], vh[15]);
            uint4* dl = (uint4*)&AsL[node * AS_PAD + ch * 16];
            dl[0] = make_uint4(vl[0],  vl[1],  vl[2],  vl[3]);
            dl[1] = make_uint4(vl[4],  vl[5],  vl[6],  vl[7]);
            dl[2] = make_uint4(vl[8],  vl[9],  vl[10], vl[11]);
            dl[3] = make_uint4(vl[12], vl[13], vl[14], vl[15]);
        }
        cp_wait0();
        __syncthreads();
        // --- tensor-core compute: 4 k8-steps x (2 m x 8 n) x 3 MMA terms ---
        #pragma unroll
        for (int k8 = 0; k8 < 32; k8 += 8) {
            uint32_t ah[2][4], al[2][4];
            #pragma unroll
            for (int m = 0; m < 2; m++) {
                int r0 = (mbase + m * 16 + g) * AS_PAD;
                int r8 = r0 + 8 * AS_PAD;
                ah[m][0] = AsH[r0 + k8 + tig];
                ah[m][1] = AsH[r8 + k8 + tig];
                ah[m][2] = AsH[r0 + k8 + tig + 4];
                ah[m][3] = AsH[r8 + k8 + tig + 4];
                al[m][0] = AsL[r0 + k8 + tig];
                al[m][1] = AsL[r8 + k8 + tig];
                al[m][2] = AsL[r0 + k8 + tig + 4];
                al[m][3] = AsL[r8 + k8 + tig + 4];
            }
            #pragma unroll
            for (int n = 0; n < 8; n++) {
                int cidx = nbase + n * 8 + g;
                uint32_t b0h = __float_as_uint(BsH[(k8 + tig    ) * BS_PAD + cidx]);
                uint32_t b1h = __float_as_uint(BsH[(k8 + tig + 4) * BS_PAD + cidx]);
                uint32_t b0l = __float_as_uint(BsL[(k8 + tig    ) * BS_PAD + cidx]);
                uint32_t b1l = __float_as_uint(BsL[(k8 + tig + 4) * BS_PAD + cidx]);
                // small terms first, then dominant
                mma_tf32(acc[0][n], al[0], b0h, b1h);
                mma_tf32(acc[0][n], ah[0], b0l, b1l);
                mma_tf32(acc[0][n], ah[0], b0h, b1h);
                mma_tf32(acc[1][n], al[1], b0h, b1h);
                mma_tf32(acc[1][n], ah[1], b0l, b1l);
                mma_tf32(acc[1][n], ah[1], b0h, b1h);
            }
        }
    }

    // --- epilogue: fragment rows g / g+8, cols tig*2, tig*2+1 ---
    #pragma unroll
    for (int m = 0; m < 2; m++) {
        int row0 = m0 + mbase + m * 16 + g;
        int row1 = row0 + 8;
        #pragma unroll
        for (int n = 0; n < 8; n++) {
            int cb = nbase + n * 8 + tig * 2;
            if (row0 < nRows)
                *(float2*)&out[row0 * F_HID + cb] = make_float2(acc[m][n][0], acc[m][n][1]);
            if (row1 < nRows)
                *(float2*)&out[row1 * F_HID + cb] = make_float2(acc[m][n][2], acc[m][n][3]);
        }
    }
}

// ---------------- aggregation init: agg[i] = dinv[i]^2 * t[i]  (self-loop fused with zeroing) ----
__global__ void agg_init_kernel(const float* __restrict__ t, float* __restrict__ agg)
{
    int idx  = blockIdx.x * blockDim.x + threadIdx.x;
    int node = idx >> 5, q = idx & 31;
    if (node >= N_NODES) return;
    float d  = g_dinv[node];
    float nrm = d * d;
    float4 v = *(const float4*)&t[node * F_HID + q * 4];
    v.x *= nrm; v.y *= nrm; v.z *= nrm; v.w *= nrm;
    *(float4*)&agg[node * F_HID + q * 4] = v;
}

// ---------------- symmetric-normalized edge scatter-add (warp per edge) ----------------
__global__ void scatter_kernel(const float* __restrict__ t, float* __restrict__ agg,
                               const int* __restrict__ row, const int* __restrict__ col)
{
    unsigned int gid = blockIdx.x * blockDim.x + threadIdx.x;
    int gw   = (int)(gid >> 5);
    int lane = threadIdx.x & 31;
    if (gw >= N_EDGES) return;
    int r = __ldg(&row[gw]);
    int c = __ldg(&col[gw]);
    float norm = g_dinv[r] * g_dinv[c];
    float4 v = *(const float4*)&t[r * F_HID + lane * 4];
    v.x *= norm; v.y *= norm; v.z *= norm; v.w *= norm;
    red_add_v4(&agg[c * F_HID + lane * 4], v);
}

// ---------------- zero fill ----------------
__global__ void zero_kernel(float* __restrict__ p, int n) {
    int i = (blockIdx.x * blockDim.x + threadIdx.x) * 4;
    if (i < n) *(float4*)&p[i] = make_float4(0.f, 0.f, 0.f, 0.f);
}

// ---------------- global mean pool (sum + count) ----------------
__global__ void pool_kernel(const float* __restrict__ h, const int* __restrict__ batch)
{
    int idx  = blockIdx.x * blockDim.x + threadIdx.x;
    int node = idx >> 5, q = idx & 31;
    if (node >= N_NODES) return;
    int g = __ldg(&batch[node]);
    float4 v = *(const float4*)&h[node * F_HID + q * 4];
    red_add_v4(&g_pool[g * F_HID + q * 4], v);
    if (q == 0) red_add_f32(&g_cnt[g], 1.0f);
}

// ---------------- readout: mean -> KAN -> out[G, LAT]  (full fp32) ----------------
__global__ void readout_kernel(float* __restrict__ out)
{
    __shared__ float feat[F_HID * 16];
    __shared__ float rbuf[8][F_LAT];
    int g = blockIdx.x, tid = threadIdx.x;
    if (tid < F_HID) {
        float cnt = fmaxf(g_cnt[g], 1.0f);
        float xv  = g_pool[g * F_HID + tid] / cnt;
        float s1, c1;
        sincosf(xv, &s1, &c1);
        int kb = tid * 16;
        feat[kb + 0] = c1; feat[kb + 8] = s1;
        float c2 = 2.f * c1, cp = 1.f, sp = 0.f, cc = c1, sc = s1;
        #pragma unroll
        for (int h = 1; h < 8; h++) {
            float cn = fmaf(c2, cc, -cp);
            float sn = fmaf(c2, sc, -sp);
            feat[kb + h] = cn; feat[kb + 8 + h] = sn;
            cp = cc; cc = cn; sp = sc; sc = sn;
        }
    }
    __syncthreads();
    int o = tid & 31, part = tid >> 5;
    float sum = 0.f;
    int k0 = part * 256;
    #pragma unroll 8
    for (int k = k0; k < k0 + 256; k++)
        sum = fmaf(feat[k], g_WtR[k * F_LAT + o], sum);
    rbuf[part][o] = sum;
    __syncthreads();
    if (tid < F_LAT) {
        float s = 0.f;
        #pragma unroll
        for (int p = 0; p < 8; p++) s += rbuf[p][tid];
        out[g * F_LAT + tid] = s;
    }
}

// ---------------- launch ----------------
extern "C" void kernel_launch(void* const* d_in, const int* in_sizes, int n_in,
                              void* d_out, int out_size)
{
    const float* features = (const float*)d_in[0];
    const int*   ei       = (const int*)d_in[1];
    const int*   batch    = (const int*)d_in[2];
    const float* W_embed  = (const float*)d_in[3];
    const float* W_mp     = (const float*)d_in[4];
    const float* W_read   = (const float*)d_in[5];
    float*       out      = (float*)d_out;

    const int* row = ei;
    const int* col = ei + N_EDGES;

    float *p_h0, *p_h1, *p_WtE_hi, *p_WtE_lo, *p_WtMP_hi, *p_WtMP_lo, *p_pool, *p_cnt;
    cudaGetSymbolAddress((void**)&p_h0,      g_h0);
    cudaGetSymbolAddress((void**)&p_h1,      g_h1);
    cudaGetSymbolAddress((void**)&p_WtE_hi,  g_WtE_hi);
    cudaGetSymbolAddress((void**)&p_WtE_lo,  g_WtE_lo);
    cudaGetSymbolAddress((void**)&p_WtMP_hi, g_WtMP_hi);
    cudaGetSymbolAddress((void**)&p_WtMP_lo, g_WtMP_lo);
    cudaGetSymbolAddress((void**)&p_pool,    g_pool);
    cudaGetSymbolAddress((void**)&p_cnt,     g_cnt);

    // opt-in to >48KB dynamic SMEM (host-side attribute; not a stream op — capture-safe)
    cudaFuncSetAttribute((const void*)kan_gemm_mma<F_IN>,
                         cudaFuncAttributeMaxDynamicSharedMemorySize, SMEM_BYTES);
    cudaFuncSetAttribute((const void*)kan_gemm_mma<F_HID>,
                         cudaFuncAttributeMaxDynamicSharedMemorySize, SMEM_BYTES);

    // weights -> k-major transposed tf32 hi/lo copies
    prep_weights<<<(SZ_WTE + SZ_WTMP + SZ_WTR + 255) / 256, 256>>>(W_embed, W_mp, W_read);

    // degrees (self-loops included) and d^-1/2
    deg_init_kernel<<<(N_NODES + 255) / 256, 256>>>();
    deg_edge_kernel<<<(N_EDGES + 255) / 256, 256>>>(col);
    dinv_kernel<<<(N_NODES + 255) / 256, 256>>>();

    const int gemm_blocks = (N_NODES + 127) / 128;

    // embed
    kan_gemm_mma<F_IN><<<gemm_blocks, 256, SMEM_BYTES>>>(features, p_WtE_hi, p_WtE_lo, p_h0, N_NODES);

    // message-passing layers: kan -> (self-loop init + edge scatter)
    for (int lay = 0; lay < N_LAYERS; lay++) {
        kan_gemm_mma<F_HID><<<gemm_blocks, 256, SMEM_BYTES>>>(
            p_h0, p_WtMP_hi + lay * (F_HID * 16 * F_HID), p_WtMP_lo + lay * (F_HID * 16 * F_HID),
            p_h1, N_NODES);
        agg_init_kernel<<<((unsigned)N_NODES * 32 + 255) / 256, 256>>>(p_h1, p_h0);
        scatter_kernel<<<((unsigned)N_EDGES * 32 + 255) / 256, 256>>>(p_h1, p_h0, row, col);
    }

    // mean pool + readout
    zero_kernel<<<(N_GRAPHS * F_HID / 4 + 255) / 256, 256>>>(p_pool, N_GRAPHS * F_HID);
    zero_kernel<<<1, 16>>>(p_cnt, N_GRAPHS);
    pool_kernel<<<((unsigned)N_NODES * 32 + 255) / 256, 256>>>(p_h0, batch);
    readout_kernel<<<N_GRAPHS, 256>>>(out);
}